// round 2
// baseline (speedup 1.0000x reference)
#include <cuda_runtime.h>
#include <cstdint>

// ---------------------------------------------------------------------------
// 2-layer LSTM, S=512, B=64, I=H=1024, fp32 with FFMA2 (fma.rn.f32x2).
//   gemm_bias:       gi = X @ W_ih^T + b_ih + b_hh   (2 launches)
//   lstm_layer:      persistent kernel, 128 CTAs, 512 steps in-kernel,
//                    grid barrier per step, W_hh slice cached in SMEM.
// 4 graph nodes total.
// ---------------------------------------------------------------------------

#define SEQ   512
#define BATCH 64
#define HID   1024
#define G4    4096
#define BH    (BATCH * HID)      // 65536
#define BG    (BATCH * G4)       // 262144
#define YSZ   (SEQ * BH)
#define HOFF  YSZ
#define COFF  (YSZ + 2 * BH)
#define FULL_OUT (YSZ + 4 * BH)
#define NCTA  128

// Scratch (__device__ globals: no allocations allowed)
__device__ __align__(16) float g_gi[SEQ * BG];   // 536 MB input projections
__device__ __align__(16) float g_y0[SEQ * BH];   // 134 MB layer-0 outputs
__device__ int          g_bar_count;             // zero-initialized at load
__device__ volatile int g_bar_gen;

// ---------------- f32x2 helpers -------------------------------------------
__device__ __forceinline__ void ffma2(unsigned long long& acc,
                                      unsigned long long a,
                                      unsigned long long b) {
    asm("fma.rn.f32x2 %0, %1, %2, %0;" : "+l"(acc) : "l"(a), "l"(b));
}
__device__ __forceinline__ unsigned long long dup2(float x) {
    unsigned long long r; unsigned u = __float_as_uint(x);
    asm("mov.b64 %0, {%1, %1};" : "=l"(r) : "r"(u));
    return r;
}
__device__ __forceinline__ float lo32(unsigned long long v) {
    return __uint_as_float((unsigned)v);
}
__device__ __forceinline__ float hi32(unsigned long long v) {
    return __uint_as_float((unsigned)(v >> 32));
}

// ---------------- cp.async helpers ----------------------------------------
__device__ __forceinline__ void cp_async16(unsigned dst, const void* src) {
    asm volatile("cp.async.cg.shared.global [%0], [%1], 16;" :: "r"(dst), "l"(src));
}
__device__ __forceinline__ void cp_commit() {
    asm volatile("cp.async.commit_group;");
}
template <int N> __device__ __forceinline__ void cp_wait() {
    asm volatile("cp.async.wait_group %0;" :: "n"(N));
}

// ---------------- fast activations ----------------------------------------
__device__ __forceinline__ float sigm(float x) {
    return 1.f / (1.f + __expf(-x));
}
__device__ __forceinline__ float tanh_f(float x) {
    // tanh(x) = 1 - 2/(exp(2x)+1)
    return 1.f - 2.f / (__expf(2.f * x) + 1.f);
}

// ---------------------------------------------------------------------------
// C[m][n] = sum_k A[m][k]*W[n][k] + b1[n] + b2[n];  N=4096, K=1024.
// 128x128 tile, 256 threads, 8x8 microtile, FFMA2 paired across n.
__global__ __launch_bounds__(256) void gemm_bias(
    const float* __restrict__ A, const float* __restrict__ W,
    const float* __restrict__ b1, const float* __restrict__ b2,
    float* __restrict__ C)
{
    __shared__ __align__(16) float As[16][132];
    __shared__ __align__(16) float Ws[16][132];
    const int tid = threadIdx.x;
    const int mb = blockIdx.y * 128;
    const int nb = blockIdx.x * 128;
    const int m0 = (tid >> 4) * 8;
    const int n0 = (tid & 15) * 8;

    unsigned long long acc2[8][4];
#pragma unroll
    for (int i = 0; i < 8; i++)
#pragma unroll
        for (int j = 0; j < 4; j++) acc2[i][j] = 0ull;

    for (int kt = 0; kt < 1024; kt += 16) {
#pragma unroll
        for (int t2 = 0; t2 < 2; t2++) {
            int li = tid + t2 * 256;            // [0,512)
            int m  = li >> 2;
            int kq = (li & 3) * 4;
            float4 va = *(const float4*)(A + (size_t)(mb + m) * 1024 + kt + kq);
            As[kq + 0][m] = va.x; As[kq + 1][m] = va.y;
            As[kq + 2][m] = va.z; As[kq + 3][m] = va.w;
            float4 vw = *(const float4*)(W + (size_t)(nb + m) * 1024 + kt + kq);
            Ws[kq + 0][m] = vw.x; Ws[kq + 1][m] = vw.y;
            Ws[kq + 2][m] = vw.z; Ws[kq + 3][m] = vw.w;
        }
        __syncthreads();
#pragma unroll
        for (int k = 0; k < 16; k++) {
            float a[8];
            *(float4*)(a)     = *(const float4*)&As[k][m0];
            *(float4*)(a + 4) = *(const float4*)&As[k][m0 + 4];
            ulonglong2 wq0 = *(const ulonglong2*)&Ws[k][n0];
            ulonglong2 wq1 = *(const ulonglong2*)&Ws[k][n0 + 4];
#pragma unroll
            for (int i = 0; i < 8; i++) {
                unsigned long long ad = dup2(a[i]);
                ffma2(acc2[i][0], ad, wq0.x);
                ffma2(acc2[i][1], ad, wq0.y);
                ffma2(acc2[i][2], ad, wq1.x);
                ffma2(acc2[i][3], ad, wq1.y);
            }
        }
        __syncthreads();
    }

    float bias[8];
#pragma unroll
    for (int j = 0; j < 8; j++) bias[j] = b1[nb + n0 + j] + b2[nb + n0 + j];
#pragma unroll
    for (int i = 0; i < 8; i++) {
        float v[8];
#pragma unroll
        for (int jp = 0; jp < 4; jp++) {
            v[2 * jp]     = lo32(acc2[i][jp]) + bias[2 * jp];
            v[2 * jp + 1] = hi32(acc2[i][jp]) + bias[2 * jp + 1];
        }
        float* cp = C + (size_t)(mb + m0 + i) * 4096 + nb + n0;
        *(float4*)cp       = make_float4(v[0], v[1], v[2], v[3]);
        *(float4*)(cp + 4) = make_float4(v[4], v[5], v[6], v[7]);
    }
}

// ---------------------------------------------------------------------------
// Grid-wide sense barrier (all 128 CTAs resident: 1 CTA/SM, grid <= 148).
__device__ __forceinline__ void grid_sync(int& phase) {
    __syncthreads();
    if (threadIdx.x == 0) {
        __threadfence();
        int old = atomicAdd(&g_bar_count, 1);
        if (old == NCTA - 1) {
            atomicExch(&g_bar_count, 0);
            __threadfence();
            g_bar_gen = phase + 1;
        } else {
            while (g_bar_gen - (phase + 1) < 0) __nanosleep(64);
            __threadfence();
        }
    }
    phase += 1;
    __syncthreads();
}

// ---------------------------------------------------------------------------
// Persistent per-layer LSTM recurrence.
// grid = 128 CTAs x 256 threads. CTA jb owns h-columns [jb*8, jb*8+8),
// i.e. 32 gate columns {g*1024 + jb*8 + jl}. W_hh slice (32x1024) cached in
// SMEM (padded stride 1028). Per step: stage h[t-1] chunks (cp.async, double
// buffered), FFMA2 GEMM paired across k, CTA-local cell update, grid barrier.
//
// SMEM floats: W 32*1028 | Hs 2*64*128 | Gs 32*68 | Cs 512  -> 207872 bytes
#define WSM_N   (32 * 1028)
#define HS_N    (2 * 64 * 128)
#define GS_N    (32 * 68)
#define LSTM_SMEM_FLOATS (WSM_N + HS_N + GS_N + 512)
#define LSTM_SMEM_BYTES  (LSTM_SMEM_FLOATS * 4)

__global__ __launch_bounds__(256) void lstm_layer_kernel(
    const float* __restrict__ Whh, const float* __restrict__ gi,
    float* __restrict__ yout, float* __restrict__ out, int layer, int full)
{
    extern __shared__ __align__(16) float smem[];
    float* Wsm = smem;
    float* Hs  = smem + WSM_N;
    float* Gs  = Hs + HS_N;
    float* Cs  = Gs + GS_N;

    const int tid = threadIdx.x;
    const int jb  = blockIdx.x;                  // 0..127

    // ---- preload W_hh slice into SMEM (once per layer) ----
#pragma unroll 4
    for (int it = 0; it < 32; it++) {
        int idx = tid + it * 256;                // 8192 float4
        int lc  = idx >> 8;                      // local gate col 0..31
        int kq  = (idx & 255) * 4;
        int row = ((lc >> 3) << 10) + jb * 8 + (lc & 7);
        float4 v = *(const float4*)(Whh + (size_t)row * 1024 + kq);
        *(float4*)(Wsm + lc * 1028 + kq) = v;
    }
    for (int i = tid; i < 512; i += 256) Cs[i] = 0.f;
    int bar_phase = g_bar_gen;                   // stable between launches
    __syncthreads();

    const int col = tid & 31;                    // local gate col
    const int b0w = (tid >> 5) * 8;              // 8 batches per thread
    const unsigned hs_u32 =
        (unsigned)__cvta_generic_to_shared(Hs);

    for (int t = 0; t < SEQ; t++) {
        if (t > 0) {
            const float* hprev = yout + (size_t)(t - 1) * BH;
            unsigned long long acc2[8];
#pragma unroll
            for (int i = 0; i < 8; i++) acc2[i] = 0ull;

            // prefetch chunk 0
#pragma unroll
            for (int q = 0; q < 8; q++) {
                int idx = tid + q * 256;
                int b = idx >> 5, kk = (idx & 31) * 4;
                cp_async16(hs_u32 + (unsigned)(b * 128 + kk) * 4,
                           hprev + (size_t)b * HID + kk);
            }
            cp_commit();

            for (int c = 0; c < 8; c++) {
                if (c < 7) {
                    int buf = (c + 1) & 1;
#pragma unroll
                    for (int q = 0; q < 8; q++) {
                        int idx = tid + q * 256;
                        int b = idx >> 5, kk = (idx & 31) * 4;
                        cp_async16(hs_u32 + (unsigned)(buf * 8192 + b * 128 + kk) * 4,
                                   hprev + (size_t)b * HID + (c + 1) * 128 + kk);
                    }
                    cp_commit();
                    cp_wait<1>();
                } else {
                    cp_wait<0>();
                }
                __syncthreads();

                const float* hb = Hs + (c & 1) * 8192;
                const float* wb = Wsm + col * 1028 + c * 128;
#pragma unroll 8
                for (int kk = 0; kk < 128; kk += 4) {
                    ulonglong2 wq = *(const ulonglong2*)(wb + kk);
#pragma unroll
                    for (int i = 0; i < 8; i++) {
                        ulonglong2 hq = *(const ulonglong2*)(hb + (b0w + i) * 128 + kk);
                        ffma2(acc2[i], hq.x, wq.x);
                        ffma2(acc2[i], hq.y, wq.y);
                    }
                }
                __syncthreads();
            }
            // stash gates (recurrent part) into Gs[col][b]
#pragma unroll
            for (int i = 0; i < 8; i++)
                Gs[col * 68 + b0w + i] = lo32(acc2[i]) + hi32(acc2[i]);
            __syncthreads();
        }

        // ---- cell update: 512 cells, 2 per thread (CTA-local) ----
        const float* gi_t = gi + (size_t)t * BG;
        float* hout = yout + (size_t)t * BH;
#pragma unroll
        for (int e = 0; e < 2; e++) {
            int idx = tid * 2 + e;               // 0..511
            int b = idx >> 3;
            int jl = idx & 7;
            int gj = jb * 8 + jl;
            float gv[4];
#pragma unroll
            for (int g = 0; g < 4; g++) {
                float r = (t > 0) ? Gs[(g * 8 + jl) * 68 + b] : 0.f;
                gv[g] = r + gi_t[(size_t)b * 4096 + (g << 10) + gj];
            }
            float si = sigm(gv[0]);
            float sf = sigm(gv[1]);
            float gt = tanh_f(gv[2]);
            float so = sigm(gv[3]);
            float cn = sf * Cs[idx] + si * gt;
            Cs[idx] = cn;
            float h = so * tanh_f(cn);
            hout[(size_t)b * HID + gj] = h;
            if (t == SEQ - 1 && full) {
                out[HOFF + (size_t)layer * BH + (size_t)b * HID + gj] = h;
                out[COFF + (size_t)layer * BH + (size_t)b * HID + gj] = cn;
            }
        }
        if (t < SEQ - 1) grid_sync(bar_phase);
    }
}

// ---------------------------------------------------------------------------
extern "C" void kernel_launch(void* const* d_in, const int* in_sizes, int n_in,
                              void* d_out, int out_size)
{
    const float* x    = (const float*)d_in[0];
    const float* wih0 = (const float*)d_in[1];
    const float* whh0 = (const float*)d_in[2];
    const float* bih0 = (const float*)d_in[3];
    const float* bhh0 = (const float*)d_in[4];
    const float* wih1 = (const float*)d_in[5];
    const float* whh1 = (const float*)d_in[6];
    const float* bih1 = (const float*)d_in[7];
    const float* bhh1 = (const float*)d_in[8];
    float* out = (float*)d_out;

    float *gi, *y0;
    cudaGetSymbolAddress((void**)&gi, g_gi);
    cudaGetSymbolAddress((void**)&y0, g_y0);

    cudaFuncSetAttribute(lstm_layer_kernel,
                         cudaFuncAttributeMaxDynamicSharedMemorySize,
                         LSTM_SMEM_BYTES);

    const int full = (out_size >= FULL_OUT) ? 1 : 0;
    dim3 ggrid(32, 256);                       // N/128 x M/128

    // Layer 0
    gemm_bias<<<ggrid, 256>>>(x, wih0, bih0, bhh0, gi);
    lstm_layer_kernel<<<NCTA, 256, LSTM_SMEM_BYTES>>>(whh0, gi, y0, out, 0, full);
    // Layer 1
    gemm_bias<<<ggrid, 256>>>(y0, wih1, bih1, bhh1, gi);
    lstm_layer_kernel<<<NCTA, 256, LSTM_SMEM_BYTES>>>(whh1, gi, out, out, 1, full);
}